// round 14
// baseline (speedup 1.0000x reference)
#include <cuda_runtime.h>
#include <cstdint>
#include <cstddef>

// Problem constants
#define N_PTS  262144      // S1*T
#define KCODES 512
#define DIM    64
#define MT     256         // points per tile
#define NT     (N_PTS / MT)   // 1024 tiles
#define THREADS 512
#define TAU    1e-4f
#define CANDM  2e-4f

// Output layout (concatenated tuple, fp32)
// NOTE: interior offsets are only 4-byte aligned in general.
// O_ENC, O_DIST are == 2 (mod 4) floats -> max vector width is float2 (8B).
static const size_t O_LOSS = 0;
static const size_t O_Q    = 1;
static const size_t O_PERP = 16777217;
static const size_t O_ENC  = 16777218;
static const size_t O_DIST = 150994946;
static const size_t O_IDX  = 285212674;

__device__ int    g_counts[512];   // zero-init; reset by last CTA each run
__device__ double g_loss;
__device__ int    g_done;

// ---- SMEM layout (bytes) ----
#define SM_XB    0          // float [256][68] x tile fp32
#define SM_EB    69632      // float [512][68] codebook fp32 (tf32 cvt on the fly)
#define SM_ESQ   208896     // float [512]
#define SM_XSQ   210944     // float [256]
#define SM_T2V1  211968     // float [256]
#define SM_T2K1  212992     // int   [256]
#define SM_T2V2  214016     // float [256]
#define SM_BK    215040     // int   [256]
#define SM_RED   216064     // double[512]
#define SM_RLIST 220160     // int   [256]
#define SM_RCNT  221184     // int
#define SM_RBEST 221192     // unsigned long long (8-aligned)
#define SM_LAST  221200     // int
#define SMEM_TOTAL 221216

static __device__ __forceinline__ uint32_t f2tf(float f) {
    uint32_t u;
    asm("cvt.rna.tf32.f32 %0, %1;" : "=r"(u) : "f"(f));
    return u;
}
static __device__ __forceinline__ void mma_tf32(float* d, const uint32_t* a,
                                                uint32_t b0, uint32_t b1) {
    asm volatile("mma.sync.aligned.m16n8k8.row.col.f32.tf32.tf32.f32 "
                 "{%0,%1,%2,%3}, {%4,%5,%6,%7}, {%8,%9}, {%0,%1,%2,%3};"
                 : "+f"(d[0]), "+f"(d[1]), "+f"(d[2]), "+f"(d[3])
                 : "r"(a[0]), "r"(a[1]), "r"(a[2]), "r"(a[3]), "r"(b0), "r"(b1));
}
static __device__ __forceinline__ void t2merge(float& v1, int& k1, float& v2,
                                               float ov1, int ok1, float ov2) {
    if (ov1 < v1 || (ov1 == v1 && ok1 < k1)) {
        v2 = fminf(v1, fminf(v2, ov2));
        v1 = ov1; k1 = ok1;
    } else {
        v2 = fminf(v2, fminf(ov1, ov2));
    }
}

__global__ __launch_bounds__(THREADS, 1)
void vq_tc(const float* __restrict__ x, const float* __restrict__ emb,
           float* __restrict__ out)
{
    extern __shared__ char smem[];
    float*    xb    = (float*)(smem + SM_XB);      // stride 68
    float*    eb    = (float*)(smem + SM_EB);      // stride 68, fp32 codebook
    float*    esq   = (float*)(smem + SM_ESQ);
    float*    xsq   = (float*)(smem + SM_XSQ);
    float*    t2v1  = (float*)(smem + SM_T2V1);
    int*      t2k1  = (int*)(smem + SM_T2K1);
    float*    t2v2  = (float*)(smem + SM_T2V2);
    int*      bk_a  = (int*)(smem + SM_BK);
    double*   red   = (double*)(smem + SM_RED);
    int*      rlist = (int*)(smem + SM_RLIST);
    int*      rcnt  = (int*)(smem + SM_RCNT);
    unsigned long long* rbest = (unsigned long long*)(smem + SM_RBEST);
    int*      lastf = (int*)(smem + SM_LAST);

    const int tid  = threadIdx.x;
    const int lane = tid & 31;
    const int w    = tid >> 5;      // 16 warps
    const int gid  = lane >> 2;     // 0..7
    const int tg   = lane & 3;      // 0..3
    const int pbase = w * 16;       // warp owns 16 points

    // ---- Codebook -> fp32 SMEM (padded stride 68); esq via reference recipe ----
    for (int i = tid; i < KCODES * DIM; i += THREADS) {
        int n = i >> 6, k = i & 63;
        eb[n * 68 + k] = emb[i];
    }
    for (int k = tid; k < KCODES; k += THREADS) {
        float s = 0.f;
        for (int d = 0; d < DIM; ++d) {
            float v = emb[k * 64 + d];
            s = __fadd_rn(s, __fmul_rn(v, v));
        }
        esq[k] = s;
    }
    __syncthreads();

    float* out_dist = out + O_DIST;
    double loss_acc = 0.0;

    for (int tile = blockIdx.x; tile < NT; tile += gridDim.x) {
        const int n0 = tile * MT;

        // ---- Load x tile into SMEM fp32 [p][d]; reset refine count ----
        if (tid == 0) *rcnt = 0;
        for (int it = 0; it < 32; ++it) {
            int d = it * 2 + (tid >> 8);
            int p = tid & 255;
            xb[p * 68 + d] = x[(size_t)d * N_PTS + n0 + p];
        }
        __syncthreads();
        // ||x_p||^2: reference recipe (rounded squares, sequential d)
        if (tid < MT) {
            float s = 0.f;
            for (int d = 0; d < DIM; ++d) {
                float v = xb[tid * 68 + d];
                s = __fadd_rn(s, __fmul_rn(v, v));
            }
            xsq[tid] = s;
        }
        __syncthreads();

        float v1s[2], v2s[2]; int k1s[2];
#pragma unroll
        for (int hh = 0; hh < 2; ++hh)
            { v1s[hh] = 3.0e38f; v2s[hh] = 3.0e38f; k1s[hh] = 1 << 30; }

        // ---- 8 passes of 64 codes; per pass: K=64 via 8 k-steps of mma ----
        for (int pass = 0; pass < 8; ++pass) {
            float acc[8][4];
#pragma unroll
            for (int nb = 0; nb < 8; ++nb)
#pragma unroll
                for (int q = 0; q < 4; ++q) acc[nb][q] = 0.f;

#pragma unroll
            for (int kk = 0; kk < 8; ++kk) {
                uint32_t afr[4];
                afr[0] = f2tf(xb[(pbase + gid) * 68 + kk * 8 + tg]);
                afr[1] = f2tf(xb[(pbase + 8 + gid) * 68 + kk * 8 + tg]);
                afr[2] = f2tf(xb[(pbase + gid) * 68 + kk * 8 + tg + 4]);
                afr[3] = f2tf(xb[(pbase + 8 + gid) * 68 + kk * 8 + tg + 4]);
                uint32_t b0[8], b1[8];
#pragma unroll
                for (int nb = 0; nb < 8; ++nb) {
                    int n = pass * 64 + nb * 8 + gid;
                    b0[nb] = f2tf(eb[n * 68 + kk * 8 + tg]);
                    b1[nb] = f2tf(eb[n * 68 + kk * 8 + tg + 4]);
                }
#pragma unroll
                for (int nb = 0; nb < 8; ++nb)
                    mma_tf32(acc[nb], afr, b0[nb], b1[nb]);
            }

            // ---- Pass epilogue: dist + store + top-2 ----
            // 2*acc is exact (power-of-2 scale), so
            // fsub(t, fmul(2,acc)) == fmaf(-2, acc, t) bit-for-bit.
            const int r0 = pbase + gid;
            const int r1 = r0 + 8;
            const float xq0 = xsq[r0], xq1 = xsq[r1];
            float* drow0 = out_dist + (size_t)(n0 + r0) * 512;
            float* drow1 = out_dist + (size_t)(n0 + r1) * 512;
#pragma unroll
            for (int nb = 0; nb < 8; ++nb) {
                const int col = pass * 64 + nb * 8 + 2 * tg;
                float2 es = *(float2*)(esq + col);
                float d00 = __fmaf_rn(-2.0f, acc[nb][0], __fadd_rn(xq0, es.x));
                float d01 = __fmaf_rn(-2.0f, acc[nb][1], __fadd_rn(xq0, es.y));
                float d10 = __fmaf_rn(-2.0f, acc[nb][2], __fadd_rn(xq1, es.x));
                float d11 = __fmaf_rn(-2.0f, acc[nb][3], __fadd_rn(xq1, es.y));
                *(float2*)(drow0 + col) = make_float2(d00, d01);
                *(float2*)(drow1 + col) = make_float2(d10, d11);
                // ascending col order -> strict < keeps first index
                if (d00 < v1s[0]) { v2s[0] = v1s[0]; v1s[0] = d00; k1s[0] = col; }
                else if (d00 < v2s[0]) v2s[0] = d00;
                if (d01 < v1s[0]) { v2s[0] = v1s[0]; v1s[0] = d01; k1s[0] = col + 1; }
                else if (d01 < v2s[0]) v2s[0] = d01;
                if (d10 < v1s[1]) { v2s[1] = v1s[1]; v1s[1] = d10; k1s[1] = col; }
                else if (d10 < v2s[1]) v2s[1] = d10;
                if (d11 < v1s[1]) { v2s[1] = v1s[1]; v1s[1] = d11; k1s[1] = col + 1; }
                else if (d11 < v2s[1]) v2s[1] = d11;
            }
        }

        // ---- Reduce top-2 across the 4 tg-lanes sharing each row ----
#pragma unroll
        for (int hh = 0; hh < 2; ++hh) {
            float v1 = v1s[hh], v2 = v2s[hh]; int k1 = k1s[hh];
#pragma unroll
            for (int off = 1; off <= 2; off <<= 1) {
                float ov1 = __shfl_xor_sync(0xffffffffu, v1, off);
                int   ok1 = __shfl_xor_sync(0xffffffffu, k1, off);
                float ov2 = __shfl_xor_sync(0xffffffffu, v2, off);
                t2merge(v1, k1, v2, ov1, ok1, ov2);
            }
            if (tg == 0) {
                int row = pbase + hh * 8 + gid;
                t2v1[row] = v1; t2k1[row] = k1; t2v2[row] = v2;
            }
        }
        __syncthreads();

        // ---- Classify: clean points done immediately, near-ties listed ----
        if (tid < MT) {
            float m1 = t2v1[tid], m2 = t2v2[tid];
            if (m2 - m1 < TAU) {
                int pos = atomicAdd(rcnt, 1);
                rlist[pos] = tid;
            } else {
                int bk = t2k1[tid];
                bk_a[tid] = bk;
                out[O_IDX + n0 + tid] = (float)bk;
                atomicAdd(&g_counts[bk], 1);
            }
        }
        __syncthreads();

        // ---- Cooperative fp64 refinement: whole CTA per flagged point ----
        const int nf = *rcnt;
        for (int i = 0; i < nf; ++i) {
            const int p = rlist[i];
            if (tid == 0) *rbest = 0xFFFFFFFFFFFFFFFFull;
            __syncthreads();
            const float m1p = t2v1[p];
            const float mxq = xsq[p];
            // thread tid screens code k = tid (coalesced L2-hot row read)
            float dv = out_dist[(size_t)(n0 + p) * 512 + tid];
            if (dv < m1p + CANDM) {
                double d0 = 0.0, d1 = 0.0, d2 = 0.0, d3 = 0.0;
                const float* xp = xb + p * 68;
                const float* ep = eb + tid * 68;
#pragma unroll 4
                for (int d = 0; d < DIM; d += 4) {
                    d0 = fma((double)xp[d],     (double)ep[d],     d0);
                    d1 = fma((double)xp[d + 1], (double)ep[d + 1], d1);
                    d2 = fma((double)xp[d + 2], (double)ep[d + 2], d2);
                    d3 = fma((double)xp[d + 3], (double)ep[d + 3], d3);
                }
                double dd = (d0 + d1) + (d2 + d3);
                float df = __fsub_rn(__fadd_rn(mxq, esq[tid]),
                                     __fmul_rn(2.0f, (float)dd));
                // positive floats: bit pattern monotonic; low word = index
                unsigned long long key =
                    ((unsigned long long)__float_as_uint(df) << 32) | (unsigned)tid;
                atomicMin(rbest, key);
            }
            __syncthreads();
            if (tid == 0) {
                int bk = (int)(*rbest & 0xFFFFFFFFull);
                bk_a[p] = bk;
                out[O_IDX + n0 + p] = (float)bk;
                atomicAdd(&g_counts[bk], 1);
            }
        }
        __syncthreads();

        // ---- Quantized (straight-through) + loss, layout [d][n] ----
        {
            const int p = tid & 255;
            const int dbase = tid >> 8;
            const int k = bk_a[p];          // loop-invariant, loaded once
            for (int it = 0; it < 32; ++it) {
                int d = it * 2 + dbase;
                float xv = xb[p * 68 + d];
                float qv = eb[k * 68 + d];
                float diff = __fsub_rn(qv, xv);
                out[O_Q + (size_t)d * N_PTS + n0 + p] = __fadd_rn(xv, diff);
                loss_acc += (double)diff * (double)diff;
            }
        }

        // ---- One-hot encodings: streaming zeros, then scatter the 1s ----
        {
            float* encp = out + O_ENC;
            const int c0 = (tid & 255) * 2;   // column pair 0..510
            const int psub = tid >> 8;        // 0..1
            const float2 z2 = make_float2(0.f, 0.f);
            for (int it = 0; it < 128; ++it) {
                int p = it * 2 + psub;
                *(float2*)(encp + (size_t)(n0 + p) * 512 + c0) = z2;
            }
            __syncthreads();                  // zeros drained before the 1s
            if (tid < MT)
                encp[(size_t)(n0 + tid) * 512 + bk_a[tid]] = 1.0f;
        }
        __syncthreads();   // protect xb/bk/t2 before next tile
    }

    // ---- CTA loss contribution ----
    for (int off = 16; off; off >>= 1)
        loss_acc += __shfl_down_sync(0xffffffffu, loss_acc, off);
    if (lane == 0) red[w] = loss_acc;
    __syncthreads();
    if (tid == 0) {
        double s = 0.0;
        for (int i = 0; i < 16; ++i) s += red[i];
        atomicAdd(&g_loss, s);
    }

    // ---- Last-CTA final reduction + global state reset (replay-safe) ----
    __threadfence();
    __syncthreads();
    if (tid == 0) {
        int t = atomicAdd(&g_done, 1);
        *lastf = (t == (int)gridDim.x - 1);
    }
    __syncthreads();
    if (*lastf) {
        int c = atomicAdd(&g_counts[tid], 0);     // tid == code (512 == 512)
        double pr = (double)c * (1.0 / 262144.0);
        red[tid] = pr * log(pr + 1e-10);
        atomicExch(&g_counts[tid], 0);            // reset for next replay
        __syncthreads();
        for (int st = 256; st; st >>= 1) {
            if (tid < st) red[tid] += red[tid + st];
            __syncthreads();
        }
        if (tid == 0) {
            double L = atomicAdd(&g_loss, 0.0);
            out[O_PERP] = (float)exp(-red[0]);
            float m = (float)(L * (1.0 / 16777216.0));
            out[O_LOSS] = m + 0.25f * m;          // q_latent + 0.25 * e_latent
            atomicExch((unsigned long long*)&g_loss, 0ull);
            atomicExch(&g_done, 0);
        }
    }
}

extern "C" void kernel_launch(void* const* d_in, const int* in_sizes, int n_in,
                              void* d_out, int out_size)
{
    const float* x   = (const float*)d_in[0];   // (64, 32, 8192) fp32
    const float* emb = (const float*)d_in[1];   // (512, 64) fp32
    float* out = (float*)d_out;

    cudaFuncSetAttribute(vq_tc, cudaFuncAttributeMaxDynamicSharedMemorySize, SMEM_TOTAL);
    vq_tc<<<148, THREADS, SMEM_TOTAL>>>(x, emb, out);
}

// round 15
// speedup vs baseline: 1.0492x; 1.0492x over previous
#include <cuda_runtime.h>
#include <cstdint>
#include <cstddef>

// Problem constants
#define N_PTS  262144      // S1*T
#define KCODES 512
#define DIM    64
#define MT     256         // points per tile (two independent 128-pt halves)
#define NT     (N_PTS / MT)   // 1024 tiles
#define THREADS 512
#define TAU    1e-4f
#define CANDM  2e-4f

// Output layout (concatenated tuple, fp32)
// NOTE: interior offsets are only 4-byte aligned in general.
// O_ENC, O_DIST are == 2 (mod 4) floats -> max vector width is float2 (8B).
static const size_t O_LOSS = 0;
static const size_t O_Q    = 1;
static const size_t O_PERP = 16777217;
static const size_t O_ENC  = 16777218;
static const size_t O_DIST = 150994946;
static const size_t O_IDX  = 285212674;

__device__ int    g_counts[512];   // zero-init; reset by last CTA each run
__device__ double g_loss;
__device__ int    g_done;

// ---- SMEM layout (bytes) ----
#define SM_XB    0          // float [256][68] x tile fp32
#define SM_EB    69632      // float [512][68] codebook fp32 (tf32 cvt on the fly)
#define SM_ESQ   208896     // float [512]
#define SM_XSQ   210944     // float [256]
#define SM_T2V1  211968     // float [256]
#define SM_T2K1  212992     // int   [256]
#define SM_T2V2  214016     // float [256]
#define SM_BK    215040     // int   [256]
#define SM_RED   216064     // double[512]
#define SM_RLIST 220160     // int   [2][128]
#define SM_RCNT  221184     // int   [2]
#define SM_RBEST 221192     // ull   [2] (8-aligned)
#define SM_LAST  221208     // int
#define SMEM_TOTAL 221216

static __device__ __forceinline__ uint32_t f2tf(float f) {
    uint32_t u;
    asm("cvt.rna.tf32.f32 %0, %1;" : "=r"(u) : "f"(f));
    return u;
}
static __device__ __forceinline__ void mma_tf32(float* d, const uint32_t* a,
                                                uint32_t b0, uint32_t b1) {
    asm volatile("mma.sync.aligned.m16n8k8.row.col.f32.tf32.tf32.f32 "
                 "{%0,%1,%2,%3}, {%4,%5,%6,%7}, {%8,%9}, {%0,%1,%2,%3};"
                 : "+f"(d[0]), "+f"(d[1]), "+f"(d[2]), "+f"(d[3])
                 : "r"(a[0]), "r"(a[1]), "r"(a[2]), "r"(a[3]), "r"(b0), "r"(b1));
}
static __device__ __forceinline__ void t2merge(float& v1, int& k1, float& v2,
                                               float ov1, int ok1, float ov2) {
    if (ov1 < v1 || (ov1 == v1 && ok1 < k1)) {
        v2 = fminf(v1, fminf(v2, ov2));
        v1 = ov1; k1 = ok1;
    } else {
        v2 = fminf(v2, fminf(ov1, ov2));
    }
}
// half-scoped barrier: 256 threads, ids 1 and 2
static __device__ __forceinline__ void barh(int h) {
    asm volatile("bar.sync %0, 256;" :: "r"(1 + h) : "memory");
}

__global__ __launch_bounds__(THREADS, 1)
void vq_tc(const float* __restrict__ x, const float* __restrict__ emb,
           float* __restrict__ out)
{
    extern __shared__ char smem[];
    float*    xb    = (float*)(smem + SM_XB);      // stride 68
    float*    eb    = (float*)(smem + SM_EB);      // stride 68, fp32 codebook
    float*    esq   = (float*)(smem + SM_ESQ);
    float*    xsq   = (float*)(smem + SM_XSQ);
    float*    t2v1  = (float*)(smem + SM_T2V1);
    int*      t2k1  = (int*)(smem + SM_T2K1);
    float*    t2v2  = (float*)(smem + SM_T2V2);
    int*      bk_a  = (int*)(smem + SM_BK);
    double*   red   = (double*)(smem + SM_RED);
    int*      rlist = (int*)(smem + SM_RLIST);     // [2][128]
    int*      rcnt  = (int*)(smem + SM_RCNT);      // [2]
    unsigned long long* rbest = (unsigned long long*)(smem + SM_RBEST); // [2]
    int*      lastf = (int*)(smem + SM_LAST);

    const int tid   = threadIdx.x;
    const int lane  = tid & 31;
    const int w     = tid >> 5;      // 16 warps
    const int gid   = lane >> 2;     // 0..7
    const int tg    = lane & 3;      // 0..3
    const int pbase = w * 16;        // warp owns 16 points (warps 0-7: half 0)
    const int h     = tid >> 8;      // half id 0/1
    const int tid_h = tid & 255;     // tid within half
    const int hbase = h * 128;       // half's point base

    // ---- Codebook -> fp32 SMEM (padded stride 68); esq via reference recipe ----
    for (int i = tid; i < KCODES * DIM; i += THREADS) {
        int n = i >> 6, k = i & 63;
        eb[n * 68 + k] = emb[i];
    }
    for (int k = tid; k < KCODES; k += THREADS) {
        float s = 0.f;
        for (int d = 0; d < DIM; ++d) {
            float v = emb[k * 64 + d];
            s = __fadd_rn(s, __fmul_rn(v, v));
        }
        esq[k] = s;
    }
    __syncthreads();

    float* out_dist = out + O_DIST;
    double loss_acc = 0.0;

    for (int tile = blockIdx.x; tile < NT; tile += gridDim.x) {
        const int n0 = tile * MT;

        // ---- Half-local: reset refine count, load this half's 128 x rows ----
        if (tid_h == 0) rcnt[h] = 0;
        {
            const int p = tid_h & 127;          // 0..127
            const int dsub = tid_h >> 7;        // 0..1
            for (int it = 0; it < 32; ++it) {
                int d = it * 2 + dsub;
                xb[(hbase + p) * 68 + d] = x[(size_t)d * N_PTS + n0 + hbase + p];
            }
        }
        barh(h);
        // ---- ||x_p||^2: reference recipe (rounded squares, sequential d) ----
        if (tid_h < 128) {
            const int row = hbase + tid_h;
            float s = 0.f;
            for (int d = 0; d < DIM; ++d) {
                float v = xb[row * 68 + d];
                s = __fadd_rn(s, __fmul_rn(v, v));
            }
            xsq[row] = s;
        }
        barh(h);

        float v1s[2], v2s[2]; int k1s[2];
#pragma unroll
        for (int hh = 0; hh < 2; ++hh)
            { v1s[hh] = 3.0e38f; v2s[hh] = 3.0e38f; k1s[hh] = 1 << 30; }

        // ---- 8 passes of 64 codes; per pass: K=64 via 8 k-steps of mma ----
        for (int pass = 0; pass < 8; ++pass) {
            float acc[8][4];
#pragma unroll
            for (int nb = 0; nb < 8; ++nb)
#pragma unroll
                for (int q = 0; q < 4; ++q) acc[nb][q] = 0.f;

#pragma unroll
            for (int kk = 0; kk < 8; ++kk) {
                uint32_t afr[4];
                afr[0] = f2tf(xb[(pbase + gid) * 68 + kk * 8 + tg]);
                afr[1] = f2tf(xb[(pbase + 8 + gid) * 68 + kk * 8 + tg]);
                afr[2] = f2tf(xb[(pbase + gid) * 68 + kk * 8 + tg + 4]);
                afr[3] = f2tf(xb[(pbase + 8 + gid) * 68 + kk * 8 + tg + 4]);
                uint32_t b0[8], b1[8];
#pragma unroll
                for (int nb = 0; nb < 8; ++nb) {
                    int n = pass * 64 + nb * 8 + gid;
                    b0[nb] = f2tf(eb[n * 68 + kk * 8 + tg]);
                    b1[nb] = f2tf(eb[n * 68 + kk * 8 + tg + 4]);
                }
#pragma unroll
                for (int nb = 0; nb < 8; ++nb)
                    mma_tf32(acc[nb], afr, b0[nb], b1[nb]);
            }

            // ---- Pass epilogue: dist + store + top-2 ----
            // 2*acc exact (power-of-2) -> fmaf(-2,acc,t) == fsub(t,fmul(2,acc))
            const int r0 = pbase + gid;
            const int r1 = r0 + 8;
            const float xq0 = xsq[r0], xq1 = xsq[r1];
            float* drow0 = out_dist + (size_t)(n0 + r0) * 512;
            float* drow1 = out_dist + (size_t)(n0 + r1) * 512;
#pragma unroll
            for (int nb = 0; nb < 8; ++nb) {
                const int col = pass * 64 + nb * 8 + 2 * tg;
                float2 es = *(float2*)(esq + col);
                float d00 = __fmaf_rn(-2.0f, acc[nb][0], __fadd_rn(xq0, es.x));
                float d01 = __fmaf_rn(-2.0f, acc[nb][1], __fadd_rn(xq0, es.y));
                float d10 = __fmaf_rn(-2.0f, acc[nb][2], __fadd_rn(xq1, es.x));
                float d11 = __fmaf_rn(-2.0f, acc[nb][3], __fadd_rn(xq1, es.y));
                *(float2*)(drow0 + col) = make_float2(d00, d01);
                *(float2*)(drow1 + col) = make_float2(d10, d11);
                // ascending col order -> strict < keeps first index
                if (d00 < v1s[0]) { v2s[0] = v1s[0]; v1s[0] = d00; k1s[0] = col; }
                else if (d00 < v2s[0]) v2s[0] = d00;
                if (d01 < v1s[0]) { v2s[0] = v1s[0]; v1s[0] = d01; k1s[0] = col + 1; }
                else if (d01 < v2s[0]) v2s[0] = d01;
                if (d10 < v1s[1]) { v2s[1] = v1s[1]; v1s[1] = d10; k1s[1] = col; }
                else if (d10 < v2s[1]) v2s[1] = d10;
                if (d11 < v1s[1]) { v2s[1] = v1s[1]; v1s[1] = d11; k1s[1] = col + 1; }
                else if (d11 < v2s[1]) v2s[1] = d11;
            }
        }

        // ---- Reduce top-2 across the 4 tg-lanes sharing each row ----
#pragma unroll
        for (int hh = 0; hh < 2; ++hh) {
            float v1 = v1s[hh], v2 = v2s[hh]; int k1 = k1s[hh];
#pragma unroll
            for (int off = 1; off <= 2; off <<= 1) {
                float ov1 = __shfl_xor_sync(0xffffffffu, v1, off);
                int   ok1 = __shfl_xor_sync(0xffffffffu, k1, off);
                float ov2 = __shfl_xor_sync(0xffffffffu, v2, off);
                t2merge(v1, k1, v2, ov1, ok1, ov2);
            }
            if (tg == 0) {
                int row = pbase + hh * 8 + gid;
                t2v1[row] = v1; t2k1[row] = k1; t2v2[row] = v2;
            }
        }
        barh(h);

        // ---- Classify (half-local): clean done now, near-ties listed ----
        if (tid_h < 128) {
            const int row = hbase + tid_h;
            float m1 = t2v1[row], m2 = t2v2[row];
            if (m2 - m1 < TAU) {
                int pos = atomicAdd(&rcnt[h], 1);
                rlist[h * 128 + pos] = row;
            } else {
                int bk = t2k1[row];
                bk_a[row] = bk;
                out[O_IDX + n0 + row] = (float)bk;
                atomicAdd(&g_counts[bk], 1);
            }
        }
        barh(h);

        // ---- Cooperative fp64 refinement: half-CTA per flagged point,
        //      each thread screens 2 codes (float2 of the L2-hot dist row) ----
        const int nf = rcnt[h];
        for (int i = 0; i < nf; ++i) {
            const int p = rlist[h * 128 + i];
            if (tid_h == 0) rbest[h] = 0xFFFFFFFFFFFFFFFFull;
            barh(h);
            const float m1p = t2v1[p];
            const float mxq = xsq[p];
            float2 dv2 = *(float2*)(out_dist + (size_t)(n0 + p) * 512 + 2 * tid_h);
#pragma unroll
            for (int half2 = 0; half2 < 2; ++half2) {
                const int k = 2 * tid_h + half2;
                float dv = half2 ? dv2.y : dv2.x;
                if (dv < m1p + CANDM) {
                    double d0 = 0.0, d1 = 0.0, d2 = 0.0, d3 = 0.0;
                    const float* xp = xb + p * 68;
                    const float* ep = eb + k * 68;
#pragma unroll 4
                    for (int d = 0; d < DIM; d += 4) {
                        d0 = fma((double)xp[d],     (double)ep[d],     d0);
                        d1 = fma((double)xp[d + 1], (double)ep[d + 1], d1);
                        d2 = fma((double)xp[d + 2], (double)ep[d + 2], d2);
                        d3 = fma((double)xp[d + 3], (double)ep[d + 3], d3);
                    }
                    double dd = (d0 + d1) + (d2 + d3);
                    float df = __fsub_rn(__fadd_rn(mxq, esq[k]),
                                         __fmul_rn(2.0f, (float)dd));
                    // positive floats: bit pattern monotonic; low word = index
                    unsigned long long key =
                        ((unsigned long long)__float_as_uint(df) << 32) | (unsigned)k;
                    atomicMin(&rbest[h], key);
                }
            }
            barh(h);
            if (tid_h == 0) {
                int bk = (int)(rbest[h] & 0xFFFFFFFFull);
                bk_a[p] = bk;
                out[O_IDX + n0 + p] = (float)bk;
                atomicAdd(&g_counts[bk], 1);
            }
        }
        barh(h);

        // ---- Quantized (straight-through) + loss, layout [d][n] ----
        {
            const int p = hbase + (tid_h & 127);
            const int dbase = tid_h >> 7;
            const int k = bk_a[p];          // loop-invariant
            for (int it = 0; it < 32; ++it) {
                int d = it * 2 + dbase;
                float xv = xb[p * 68 + d];
                float qv = eb[k * 68 + d];
                float diff = __fsub_rn(qv, xv);
                out[O_Q + (size_t)d * N_PTS + n0 + p] = __fadd_rn(xv, diff);
                loss_acc += (double)diff * (double)diff;
            }
        }

        // ---- One-hot encodings (half-local, R11 style float2 rows) ----
        {
            float* encp = out + O_ENC;
            const int c0 = tid_h * 2;       // column pair 0..510
            for (int it = 0; it < 128; ++it) {
                int p = hbase + it;
                int k = bk_a[p];
                *(float2*)(encp + (size_t)(n0 + p) * 512 + c0) =
                    make_float2(c0 == k ? 1.f : 0.f, c0 + 1 == k ? 1.f : 0.f);
            }
        }
        barh(h);   // protect this half's xb/bk/t2/rcnt before next tile
    }

    // ---- CTA loss contribution ----
    __syncthreads();
    for (int off = 16; off; off >>= 1)
        loss_acc += __shfl_down_sync(0xffffffffu, loss_acc, off);
    if (lane == 0) red[w] = loss_acc;
    __syncthreads();
    if (tid == 0) {
        double s = 0.0;
        for (int i = 0; i < 16; ++i) s += red[i];
        atomicAdd(&g_loss, s);
    }

    // ---- Last-CTA final reduction + global state reset (replay-safe) ----
    __threadfence();
    __syncthreads();
    if (tid == 0) {
        int t = atomicAdd(&g_done, 1);
        *lastf = (t == (int)gridDim.x - 1);
    }
    __syncthreads();
    if (*lastf) {
        int c = atomicAdd(&g_counts[tid], 0);     // tid == code (512 == 512)
        double pr = (double)c * (1.0 / 262144.0);
        red[tid] = pr * log(pr + 1e-10);
        atomicExch(&g_counts[tid], 0);            // reset for next replay
        __syncthreads();
        for (int st = 256; st; st >>= 1) {
            if (tid < st) red[tid] += red[tid + st];
            __syncthreads();
        }
        if (tid == 0) {
            double L = atomicAdd(&g_loss, 0.0);
            out[O_PERP] = (float)exp(-red[0]);
            float m = (float)(L * (1.0 / 16777216.0));
            out[O_LOSS] = m + 0.25f * m;          // q_latent + 0.25 * e_latent
            atomicExch((unsigned long long*)&g_loss, 0ull);
            atomicExch(&g_done, 0);
        }
    }
}

extern "C" void kernel_launch(void* const* d_in, const int* in_sizes, int n_in,
                              void* d_out, int out_size)
{
    const float* x   = (const float*)d_in[0];   // (64, 32, 8192) fp32
    const float* emb = (const float*)d_in[1];   // (512, 64) fp32
    float* out = (float*)d_out;

    cudaFuncSetAttribute(vq_tc, cudaFuncAttributeMaxDynamicSharedMemorySize, SMEM_TOTAL);
    vq_tc<<<148, THREADS, SMEM_TOTAL>>>(x, emb, out);
}

// round 16
// speedup vs baseline: 1.0580x; 1.0083x over previous
#include <cuda_runtime.h>
#include <cstdint>
#include <cstddef>

// Problem constants
#define N_PTS  262144      // S1*T
#define KCODES 512
#define DIM    64
#define MT     256         // points per tile
#define NT     (N_PTS / MT)   // 1024 tiles
#define THREADS 512
#define TAU    1e-4f
#define CANDM  2e-4f

// Output layout (concatenated tuple, fp32)
// NOTE: interior offsets are only 4-byte aligned in general.
// O_ENC, O_DIST are == 2 (mod 4) floats -> max vector width is float2 (8B).
static const size_t O_LOSS = 0;
static const size_t O_Q    = 1;
static const size_t O_PERP = 16777217;
static const size_t O_ENC  = 16777218;
static const size_t O_DIST = 150994946;
static const size_t O_IDX  = 285212674;

__device__ int    g_counts[512];   // zero-init; reset by last CTA each run
__device__ double g_loss;
__device__ int    g_done;

// ---- SMEM layout (bytes) ----
#define SM_XB    0          // float [256][68] x tile fp32
#define SM_EB    69632      // float [512][68] codebook fp32 (tf32 cvt on the fly)
#define SM_ESQ   208896     // float [512]
#define SM_XSQ   210944     // float [256]
#define SM_T2V1  211968     // float [256]
#define SM_T2K1  212992     // int   [256]
#define SM_T2V2  214016     // float [256]
#define SM_BK    215040     // int   [256]
#define SM_RED   216064     // double[512]
#define SM_RLIST 220160     // int   [256]
#define SM_RCNT  221184     // int
#define SM_RBEST 221192     // unsigned long long (8-aligned)
#define SM_LAST  221200     // int
#define SMEM_TOTAL 221216

static __device__ __forceinline__ uint32_t f2tf(float f) {
    uint32_t u;
    asm("cvt.rna.tf32.f32 %0, %1;" : "=r"(u) : "f"(f));
    return u;
}
static __device__ __forceinline__ void mma_tf32(float* d, const uint32_t* a,
                                                uint32_t b0, uint32_t b1) {
    asm volatile("mma.sync.aligned.m16n8k8.row.col.f32.tf32.tf32.f32 "
                 "{%0,%1,%2,%3}, {%4,%5,%6,%7}, {%8,%9}, {%0,%1,%2,%3};"
                 : "+f"(d[0]), "+f"(d[1]), "+f"(d[2]), "+f"(d[3])
                 : "r"(a[0]), "r"(a[1]), "r"(a[2]), "r"(a[3]), "r"(b0), "r"(b1));
}
static __device__ __forceinline__ void t2merge(float& v1, int& k1, float& v2,
                                               float ov1, int ok1, float ov2) {
    if (ov1 < v1 || (ov1 == v1 && ok1 < k1)) {
        v2 = fminf(v1, fminf(v2, ov2));
        v1 = ov1; k1 = ok1;
    } else {
        v2 = fminf(v2, fminf(ov1, ov2));
    }
}

__global__ __launch_bounds__(THREADS, 1)
void vq_tc(const float* __restrict__ x, const float* __restrict__ emb,
           float* __restrict__ out)
{
    extern __shared__ char smem[];
    float*    xb    = (float*)(smem + SM_XB);      // stride 68
    float*    eb    = (float*)(smem + SM_EB);      // stride 68, fp32 codebook
    float*    esq   = (float*)(smem + SM_ESQ);
    float*    xsq   = (float*)(smem + SM_XSQ);
    float*    t2v1  = (float*)(smem + SM_T2V1);
    int*      t2k1  = (int*)(smem + SM_T2K1);
    float*    t2v2  = (float*)(smem + SM_T2V2);
    int*      bk_a  = (int*)(smem + SM_BK);
    double*   red   = (double*)(smem + SM_RED);
    int*      rlist = (int*)(smem + SM_RLIST);
    int*      rcnt  = (int*)(smem + SM_RCNT);
    unsigned long long* rbest = (unsigned long long*)(smem + SM_RBEST);
    int*      lastf = (int*)(smem + SM_LAST);

    const int tid  = threadIdx.x;
    const int lane = tid & 31;
    const int w    = tid >> 5;      // 16 warps
    const int gid  = lane >> 2;     // 0..7
    const int tg   = lane & 3;      // 0..3
    const int pbase = w * 16;       // warp owns 16 points

    // ---- Codebook -> fp32 SMEM (padded stride 68); esq via reference recipe ----
    for (int i = tid; i < KCODES * DIM; i += THREADS) {
        int n = i >> 6, k = i & 63;
        eb[n * 68 + k] = emb[i];
    }
    for (int k = tid; k < KCODES; k += THREADS) {
        float s = 0.f;
        for (int d = 0; d < DIM; ++d) {
            float v = emb[k * 64 + d];
            s = __fadd_rn(s, __fmul_rn(v, v));
        }
        esq[k] = s;
    }
    __syncthreads();

    float* out_dist = out + O_DIST;
    double loss_acc = 0.0;

    for (int tile = blockIdx.x; tile < NT; tile += gridDim.x) {
        const int n0 = tile * MT;

        // ---- Load x tile into SMEM fp32 [p][d]; reset refine count ----
        if (tid == 0) *rcnt = 0;
        for (int it = 0; it < 32; ++it) {
            int d = it * 2 + (tid >> 8);
            int p = tid & 255;
            xb[p * 68 + d] = x[(size_t)d * N_PTS + n0 + p];
        }
        __syncthreads();
        // ||x_p||^2: reference recipe (rounded squares, sequential d)
        if (tid < MT) {
            float s = 0.f;
            for (int d = 0; d < DIM; ++d) {
                float v = xb[tid * 68 + d];
                s = __fadd_rn(s, __fmul_rn(v, v));
            }
            xsq[tid] = s;
        }
        __syncthreads();

        float v1s[2], v2s[2]; int k1s[2];
#pragma unroll
        for (int hh = 0; hh < 2; ++hh)
            { v1s[hh] = 3.0e38f; v2s[hh] = 3.0e38f; k1s[hh] = 1 << 30; }

        // ---- 8 passes of 64 codes; per pass: K=64 via 8 k-steps of mma ----
        for (int pass = 0; pass < 8; ++pass) {
            float acc[8][4];
#pragma unroll
            for (int nb = 0; nb < 8; ++nb)
#pragma unroll
                for (int q = 0; q < 4; ++q) acc[nb][q] = 0.f;

#pragma unroll
            for (int kk = 0; kk < 8; ++kk) {
                uint32_t afr[4];
                afr[0] = f2tf(xb[(pbase + gid) * 68 + kk * 8 + tg]);
                afr[1] = f2tf(xb[(pbase + 8 + gid) * 68 + kk * 8 + tg]);
                afr[2] = f2tf(xb[(pbase + gid) * 68 + kk * 8 + tg + 4]);
                afr[3] = f2tf(xb[(pbase + 8 + gid) * 68 + kk * 8 + tg + 4]);
                uint32_t b0[8], b1[8];
#pragma unroll
                for (int nb = 0; nb < 8; ++nb) {
                    int n = pass * 64 + nb * 8 + gid;
                    b0[nb] = f2tf(eb[n * 68 + kk * 8 + tg]);
                    b1[nb] = f2tf(eb[n * 68 + kk * 8 + tg + 4]);
                }
#pragma unroll
                for (int nb = 0; nb < 8; ++nb)
                    mma_tf32(acc[nb], afr, b0[nb], b1[nb]);
            }

            // ---- Pass epilogue: dist + store + top-2 ----
            // 2*acc is exact (power-of-2 scale), so
            // fmaf(-2, acc, t) == fsub(t, fmul(2, acc)) bit-for-bit.
            const int r0 = pbase + gid;
            const int r1 = r0 + 8;
            const float xq0 = xsq[r0], xq1 = xsq[r1];
            float* drow0 = out_dist + (size_t)(n0 + r0) * 512;
            float* drow1 = out_dist + (size_t)(n0 + r1) * 512;
#pragma unroll
            for (int nb = 0; nb < 8; ++nb) {
                const int col = pass * 64 + nb * 8 + 2 * tg;
                float2 es = *(float2*)(esq + col);
                float d00 = __fmaf_rn(-2.0f, acc[nb][0], __fadd_rn(xq0, es.x));
                float d01 = __fmaf_rn(-2.0f, acc[nb][1], __fadd_rn(xq0, es.y));
                float d10 = __fmaf_rn(-2.0f, acc[nb][2], __fadd_rn(xq1, es.x));
                float d11 = __fmaf_rn(-2.0f, acc[nb][3], __fadd_rn(xq1, es.y));
                *(float2*)(drow0 + col) = make_float2(d00, d01);
                *(float2*)(drow1 + col) = make_float2(d10, d11);
                // ascending col order -> strict < keeps first index
                if (d00 < v1s[0]) { v2s[0] = v1s[0]; v1s[0] = d00; k1s[0] = col; }
                else if (d00 < v2s[0]) v2s[0] = d00;
                if (d01 < v1s[0]) { v2s[0] = v1s[0]; v1s[0] = d01; k1s[0] = col + 1; }
                else if (d01 < v2s[0]) v2s[0] = d01;
                if (d10 < v1s[1]) { v2s[1] = v1s[1]; v1s[1] = d10; k1s[1] = col; }
                else if (d10 < v2s[1]) v2s[1] = d10;
                if (d11 < v1s[1]) { v2s[1] = v1s[1]; v1s[1] = d11; k1s[1] = col + 1; }
                else if (d11 < v2s[1]) v2s[1] = d11;
            }
        }

        // ---- Reduce top-2 across the 4 tg-lanes sharing each row ----
#pragma unroll
        for (int hh = 0; hh < 2; ++hh) {
            float v1 = v1s[hh], v2 = v2s[hh]; int k1 = k1s[hh];
#pragma unroll
            for (int off = 1; off <= 2; off <<= 1) {
                float ov1 = __shfl_xor_sync(0xffffffffu, v1, off);
                int   ok1 = __shfl_xor_sync(0xffffffffu, k1, off);
                float ov2 = __shfl_xor_sync(0xffffffffu, v2, off);
                t2merge(v1, k1, v2, ov1, ok1, ov2);
            }
            if (tg == 0) {
                int row = pbase + hh * 8 + gid;
                t2v1[row] = v1; t2k1[row] = k1; t2v2[row] = v2;
            }
        }
        __syncthreads();

        // ---- Classify: clean points done immediately, near-ties listed ----
        if (tid < MT) {
            float m1 = t2v1[tid], m2 = t2v2[tid];
            if (m2 - m1 < TAU) {
                int pos = atomicAdd(rcnt, 1);
                rlist[pos] = tid;
            } else {
                int bk = t2k1[tid];
                bk_a[tid] = bk;
                out[O_IDX + n0 + tid] = (float)bk;
                atomicAdd(&g_counts[bk], 1);
            }
        }
        __syncthreads();

        // ---- Cooperative fp64 refinement: whole CTA per flagged point ----
        const int nf = *rcnt;
        for (int i = 0; i < nf; ++i) {
            const int p = rlist[i];
            if (tid == 0) *rbest = 0xFFFFFFFFFFFFFFFFull;
            __syncthreads();
            const float m1p = t2v1[p];
            const float mxq = xsq[p];
            // thread tid screens code k = tid (coalesced L2-hot row read)
            float dv = out_dist[(size_t)(n0 + p) * 512 + tid];
            if (dv < m1p + CANDM) {
                double d0 = 0.0, d1 = 0.0, d2 = 0.0, d3 = 0.0;
                const float* xp = xb + p * 68;
                const float* ep = eb + tid * 68;
#pragma unroll 4
                for (int d = 0; d < DIM; d += 4) {
                    d0 = fma((double)xp[d],     (double)ep[d],     d0);
                    d1 = fma((double)xp[d + 1], (double)ep[d + 1], d1);
                    d2 = fma((double)xp[d + 2], (double)ep[d + 2], d2);
                    d3 = fma((double)xp[d + 3], (double)ep[d + 3], d3);
                }
                double dd = (d0 + d1) + (d2 + d3);
                float df = __fsub_rn(__fadd_rn(mxq, esq[tid]),
                                     __fmul_rn(2.0f, (float)dd));
                // positive floats: bit pattern monotonic; low word = index
                unsigned long long key =
                    ((unsigned long long)__float_as_uint(df) << 32) | (unsigned)tid;
                atomicMin(rbest, key);
            }
            __syncthreads();
            if (tid == 0) {
                int bk = (int)(*rbest & 0xFFFFFFFFull);
                bk_a[p] = bk;
                out[O_IDX + n0 + p] = (float)bk;
                atomicAdd(&g_counts[bk], 1);
            }
        }
        __syncthreads();

        // ---- Quantized (straight-through) + loss, layout [d][n] ----
        {
            const int p = tid & 255;
            const int dbase = tid >> 8;
            const int k = bk_a[p];          // loop-invariant, loaded once
            for (int it = 0; it < 32; ++it) {
                int d = it * 2 + dbase;
                float xv = xb[p * 68 + d];
                float qv = eb[k * 68 + d];
                float diff = __fsub_rn(qv, xv);
                out[O_Q + (size_t)d * N_PTS + n0 + p] = __fadd_rn(xv, diff);
                loss_acc += (double)diff * (double)diff;
            }
        }

        // ---- One-hot encodings: float2 stores (8B-aligned; O_ENC==2 mod 4) ----
        {
            float* encp = out + O_ENC;
            const int c0 = (tid & 255) * 2;   // column pair 0..510
            const int psub = tid >> 8;        // 0..1
            for (int it = 0; it < 128; ++it) {
                int p = it * 2 + psub;
                int k = bk_a[p];
                *(float2*)(encp + (size_t)(n0 + p) * 512 + c0) =
                    make_float2(c0 == k ? 1.f : 0.f, c0 + 1 == k ? 1.f : 0.f);
            }
        }
        __syncthreads();   // protect xb/bk/t2 before next tile
    }

    // ---- CTA loss contribution ----
    for (int off = 16; off; off >>= 1)
        loss_acc += __shfl_down_sync(0xffffffffu, loss_acc, off);
    if (lane == 0) red[w] = loss_acc;
    __syncthreads();
    if (tid == 0) {
        double s = 0.0;
        for (int i = 0; i < 16; ++i) s += red[i];
        atomicAdd(&g_loss, s);
    }

    // ---- Last-CTA final reduction + global state reset (replay-safe) ----
    __threadfence();
    __syncthreads();
    if (tid == 0) {
        int t = atomicAdd(&g_done, 1);
        *lastf = (t == (int)gridDim.x - 1);
    }
    __syncthreads();
    if (*lastf) {
        int c = atomicAdd(&g_counts[tid], 0);     // tid == code (512 == 512)
        double pr = (double)c * (1.0 / 262144.0);
        red[tid] = pr * log(pr + 1e-10);
        atomicExch(&g_counts[tid], 0);            // reset for next replay
        __syncthreads();
        for (int st = 256; st; st >>= 1) {
            if (tid < st) red[tid] += red[tid + st];
            __syncthreads();
        }
        if (tid == 0) {
            double L = atomicAdd(&g_loss, 0.0);
            out[O_PERP] = (float)exp(-red[0]);
            float m = (float)(L * (1.0 / 16777216.0));
            out[O_LOSS] = m + 0.25f * m;          // q_latent + 0.25 * e_latent
            atomicExch((unsigned long long*)&g_loss, 0ull);
            atomicExch(&g_done, 0);
        }
    }
}

extern "C" void kernel_launch(void* const* d_in, const int* in_sizes, int n_in,
                              void* d_out, int out_size)
{
    const float* x   = (const float*)d_in[0];   // (64, 32, 8192) fp32
    const float* emb = (const float*)d_in[1];   // (512, 64) fp32
    float* out = (float*)d_out;

    cudaFuncSetAttribute(vq_tc, cudaFuncAttributeMaxDynamicSharedMemorySize, SMEM_TOTAL);
    vq_tc<<<148, THREADS, SMEM_TOTAL>>>(x, emb, out);
}

// round 17
// speedup vs baseline: 1.0693x; 1.0107x over previous
#include <cuda_runtime.h>
#include <cstdint>
#include <cstddef>

// Problem constants
#define N_PTS  262144      // S1*T
#define KCODES 512
#define DIM    64
#define MT     256         // points per tile
#define NT     (N_PTS / MT)   // 1024 tiles
#define THREADS 512
#define TAU    1e-4f
#define CANDM  2e-4f

// Output layout (concatenated tuple, fp32)
// NOTE: interior offsets are only 4-byte aligned in general.
// O_ENC, O_DIST are == 2 (mod 4) floats -> max vector width is float2 (8B).
static const size_t O_LOSS = 0;
static const size_t O_Q    = 1;
static const size_t O_PERP = 16777217;
static const size_t O_ENC  = 16777218;
static const size_t O_DIST = 150994946;
static const size_t O_IDX  = 285212674;

__device__ int    g_counts[512];   // zero-init; reset by last CTA each run
__device__ double g_loss;
__device__ int    g_done;

// ---- SMEM layout (bytes) ----
#define SM_XB    0          // float [256][68] x tile fp32
#define SM_EB    69632      // float [512][68] codebook fp32
#define SM_ESQ   208896     // float [512]
#define SM_XSQ   210944     // float [256]
#define SM_T2V1  211968     // float [256]
#define SM_T2K1  212992     // int   [256]
#define SM_T2V2  214016     // float [256]
#define SM_BK    215040     // int   [256]
#define SM_RED   216064     // double[512]
#define SM_RLIST 220160     // int   [256]
#define SM_RCNT  221184     // int
#define SM_RBEST 221192     // unsigned long long (8-aligned)
#define SM_LAST  221200     // int
#define SMEM_TOTAL 221216

// The tf32 mma consumes b32 operands and ignores the low mantissa bits, so
// feeding raw fp32 bit patterns == RZ truncation to tf32 (vs cvt.rna's
// round-to-nearest). The resulting distance perturbation is <= ~1e-5 abs,
// 10x inside TAU; argmin correctness is protected by the fp64 refinement,
// which uses the EXACT fp32 values from eb/xb. This removes all in-loop
// cvt instructions (20K per tile per SM).
static __device__ __forceinline__ void mma_tf32(float* d, const uint32_t* a,
                                                uint32_t b0, uint32_t b1) {
    asm volatile("mma.sync.aligned.m16n8k8.row.col.f32.tf32.tf32.f32 "
                 "{%0,%1,%2,%3}, {%4,%5,%6,%7}, {%8,%9}, {%0,%1,%2,%3};"
                 : "+f"(d[0]), "+f"(d[1]), "+f"(d[2]), "+f"(d[3])
                 : "r"(a[0]), "r"(a[1]), "r"(a[2]), "r"(a[3]), "r"(b0), "r"(b1));
}
static __device__ __forceinline__ void t2merge(float& v1, int& k1, float& v2,
                                               float ov1, int ok1, float ov2) {
    if (ov1 < v1 || (ov1 == v1 && ok1 < k1)) {
        v2 = fminf(v1, fminf(v2, ov2));
        v1 = ov1; k1 = ok1;
    } else {
        v2 = fminf(v2, fminf(ov1, ov2));
    }
}

__global__ __launch_bounds__(THREADS, 1)
void vq_tc(const float* __restrict__ x, const float* __restrict__ emb,
           float* __restrict__ out)
{
    extern __shared__ char smem[];
    float*    xb    = (float*)(smem + SM_XB);      // stride 68
    float*    eb    = (float*)(smem + SM_EB);      // stride 68, fp32 codebook
    float*    esq   = (float*)(smem + SM_ESQ);
    float*    xsq   = (float*)(smem + SM_XSQ);
    float*    t2v1  = (float*)(smem + SM_T2V1);
    int*      t2k1  = (int*)(smem + SM_T2K1);
    float*    t2v2  = (float*)(smem + SM_T2V2);
    int*      bk_a  = (int*)(smem + SM_BK);
    double*   red   = (double*)(smem + SM_RED);
    int*      rlist = (int*)(smem + SM_RLIST);
    int*      rcnt  = (int*)(smem + SM_RCNT);
    unsigned long long* rbest = (unsigned long long*)(smem + SM_RBEST);
    int*      lastf = (int*)(smem + SM_LAST);

    const int tid  = threadIdx.x;
    const int lane = tid & 31;
    const int w    = tid >> 5;      // 16 warps
    const int gid  = lane >> 2;     // 0..7
    const int tg   = lane & 3;      // 0..3
    const int pbase = w * 16;       // warp owns 16 points

    const uint32_t* xbu = (const uint32_t*)xb;
    const uint32_t* ebu = (const uint32_t*)eb;

    // ---- Codebook -> fp32 SMEM (padded stride 68); esq via reference recipe ----
    for (int i = tid; i < KCODES * DIM; i += THREADS) {
        int n = i >> 6, k = i & 63;
        eb[n * 68 + k] = emb[i];
    }
    for (int k = tid; k < KCODES; k += THREADS) {
        float s = 0.f;
        for (int d = 0; d < DIM; ++d) {
            float v = emb[k * 64 + d];
            s = __fadd_rn(s, __fmul_rn(v, v));
        }
        esq[k] = s;
    }
    __syncthreads();

    float* out_dist = out + O_DIST;
    double loss_acc = 0.0;

    for (int tile = blockIdx.x; tile < NT; tile += gridDim.x) {
        const int n0 = tile * MT;

        // ---- Load x tile into SMEM fp32 [p][d]; reset refine count ----
        if (tid == 0) *rcnt = 0;
        for (int it = 0; it < 32; ++it) {
            int d = it * 2 + (tid >> 8);
            int p = tid & 255;
            xb[p * 68 + d] = x[(size_t)d * N_PTS + n0 + p];
        }
        __syncthreads();
        // ||x_p||^2: reference recipe (rounded squares, sequential d)
        if (tid < MT) {
            float s = 0.f;
            for (int d = 0; d < DIM; ++d) {
                float v = xb[tid * 68 + d];
                s = __fadd_rn(s, __fmul_rn(v, v));
            }
            xsq[tid] = s;
        }
        __syncthreads();

        float v1s[2], v2s[2]; int k1s[2];
#pragma unroll
        for (int hh = 0; hh < 2; ++hh)
            { v1s[hh] = 3.0e38f; v2s[hh] = 3.0e38f; k1s[hh] = 1 << 30; }

        // ---- 8 passes of 64 codes; per pass: K=64 via 8 k-steps of mma ----
        for (int pass = 0; pass < 8; ++pass) {
            float acc[8][4];
#pragma unroll
            for (int nb = 0; nb < 8; ++nb)
#pragma unroll
                for (int q = 0; q < 4; ++q) acc[nb][q] = 0.f;

#pragma unroll
            for (int kk = 0; kk < 8; ++kk) {
                uint32_t afr[4];
                afr[0] = xbu[(pbase + gid) * 68 + kk * 8 + tg];
                afr[1] = xbu[(pbase + 8 + gid) * 68 + kk * 8 + tg];
                afr[2] = xbu[(pbase + gid) * 68 + kk * 8 + tg + 4];
                afr[3] = xbu[(pbase + 8 + gid) * 68 + kk * 8 + tg + 4];
                uint32_t b0[8], b1[8];
#pragma unroll
                for (int nb = 0; nb < 8; ++nb) {
                    int n = pass * 64 + nb * 8 + gid;
                    b0[nb] = ebu[n * 68 + kk * 8 + tg];
                    b1[nb] = ebu[n * 68 + kk * 8 + tg + 4];
                }
#pragma unroll
                for (int nb = 0; nb < 8; ++nb)
                    mma_tf32(acc[nb], afr, b0[nb], b1[nb]);
            }

            // ---- Pass epilogue: dist + store + top-2 ----
            // 2*acc is exact (power-of-2 scale): fmaf(-2,acc,t) == fsub(t,2*acc)
            const int r0 = pbase + gid;
            const int r1 = r0 + 8;
            const float xq0 = xsq[r0], xq1 = xsq[r1];
            float* drow0 = out_dist + (size_t)(n0 + r0) * 512;
            float* drow1 = out_dist + (size_t)(n0 + r1) * 512;
#pragma unroll
            for (int nb = 0; nb < 8; ++nb) {
                const int col = pass * 64 + nb * 8 + 2 * tg;
                float2 es = *(float2*)(esq + col);
                float d00 = __fmaf_rn(-2.0f, acc[nb][0], __fadd_rn(xq0, es.x));
                float d01 = __fmaf_rn(-2.0f, acc[nb][1], __fadd_rn(xq0, es.y));
                float d10 = __fmaf_rn(-2.0f, acc[nb][2], __fadd_rn(xq1, es.x));
                float d11 = __fmaf_rn(-2.0f, acc[nb][3], __fadd_rn(xq1, es.y));
                *(float2*)(drow0 + col) = make_float2(d00, d01);
                *(float2*)(drow1 + col) = make_float2(d10, d11);
                // ascending col order -> strict < keeps first index
                if (d00 < v1s[0]) { v2s[0] = v1s[0]; v1s[0] = d00; k1s[0] = col; }
                else if (d00 < v2s[0]) v2s[0] = d00;
                if (d01 < v1s[0]) { v2s[0] = v1s[0]; v1s[0] = d01; k1s[0] = col + 1; }
                else if (d01 < v2s[0]) v2s[0] = d01;
                if (d10 < v1s[1]) { v2s[1] = v1s[1]; v1s[1] = d10; k1s[1] = col; }
                else if (d10 < v2s[1]) v2s[1] = d10;
                if (d11 < v1s[1]) { v2s[1] = v1s[1]; v1s[1] = d11; k1s[1] = col + 1; }
                else if (d11 < v2s[1]) v2s[1] = d11;
            }
        }

        // ---- Reduce top-2 across the 4 tg-lanes sharing each row ----
#pragma unroll
        for (int hh = 0; hh < 2; ++hh) {
            float v1 = v1s[hh], v2 = v2s[hh]; int k1 = k1s[hh];
#pragma unroll
            for (int off = 1; off <= 2; off <<= 1) {
                float ov1 = __shfl_xor_sync(0xffffffffu, v1, off);
                int   ok1 = __shfl_xor_sync(0xffffffffu, k1, off);
                float ov2 = __shfl_xor_sync(0xffffffffu, v2, off);
                t2merge(v1, k1, v2, ov1, ok1, ov2);
            }
            if (tg == 0) {
                int row = pbase + hh * 8 + gid;
                t2v1[row] = v1; t2k1[row] = k1; t2v2[row] = v2;
            }
        }
        __syncthreads();

        // ---- Classify: clean points done immediately, near-ties listed ----
        if (tid < MT) {
            float m1 = t2v1[tid], m2 = t2v2[tid];
            if (m2 - m1 < TAU) {
                int pos = atomicAdd(rcnt, 1);
                rlist[pos] = tid;
            } else {
                int bk = t2k1[tid];
                bk_a[tid] = bk;
                out[O_IDX + n0 + tid] = (float)bk;
                atomicAdd(&g_counts[bk], 1);
            }
        }
        __syncthreads();

        // ---- Cooperative fp64 refinement: whole CTA per flagged point ----
        // (uses EXACT fp32 x/e from SMEM; immune to the feed truncation)
        const int nf = *rcnt;
        for (int i = 0; i < nf; ++i) {
            const int p = rlist[i];
            if (tid == 0) *rbest = 0xFFFFFFFFFFFFFFFFull;
            __syncthreads();
            const float m1p = t2v1[p];
            const float mxq = xsq[p];
            // thread tid screens code k = tid (coalesced L2-hot row read)
            float dv = out_dist[(size_t)(n0 + p) * 512 + tid];
            if (dv < m1p + CANDM) {
                double d0 = 0.0, d1 = 0.0, d2 = 0.0, d3 = 0.0;
                const float* xp = xb + p * 68;
                const float* ep = eb + tid * 68;
#pragma unroll 4
                for (int d = 0; d < DIM; d += 4) {
                    d0 = fma((double)xp[d],     (double)ep[d],     d0);
                    d1 = fma((double)xp[d + 1], (double)ep[d + 1], d1);
                    d2 = fma((double)xp[d + 2], (double)ep[d + 2], d2);
                    d3 = fma((double)xp[d + 3], (double)ep[d + 3], d3);
                }
                double dd = (d0 + d1) + (d2 + d3);
                float df = __fsub_rn(__fadd_rn(mxq, esq[tid]),
                                     __fmul_rn(2.0f, (float)dd));
                // positive floats: bit pattern monotonic; low word = index
                unsigned long long key =
                    ((unsigned long long)__float_as_uint(df) << 32) | (unsigned)tid;
                atomicMin(rbest, key);
            }
            __syncthreads();
            if (tid == 0) {
                int bk = (int)(*rbest & 0xFFFFFFFFull);
                bk_a[p] = bk;
                out[O_IDX + n0 + p] = (float)bk;
                atomicAdd(&g_counts[bk], 1);
            }
        }
        __syncthreads();

        // ---- Quantized (straight-through) + loss, layout [d][n] ----
        {
            const int p = tid & 255;
            const int dbase = tid >> 8;
            const int k = bk_a[p];          // loop-invariant, loaded once
            for (int it = 0; it < 32; ++it) {
                int d = it * 2 + dbase;
                float xv = xb[p * 68 + d];
                float qv = eb[k * 68 + d];
                float diff = __fsub_rn(qv, xv);
                out[O_Q + (size_t)d * N_PTS + n0 + p] = __fadd_rn(xv, diff);
                loss_acc += (double)diff * (double)diff;
            }
        }

        // ---- One-hot encodings: float2 stores (8B-aligned; O_ENC==2 mod 4) ----
        {
            float* encp = out + O_ENC;
            const int c0 = (tid & 255) * 2;   // column pair 0..510
            const int psub = tid >> 8;        // 0..1
            for (int it = 0; it < 128; ++it) {
                int p = it * 2 + psub;
                int k = bk_a[p];
                *(float2*)(encp + (size_t)(n0 + p) * 512 + c0) =
                    make_float2(c0 == k ? 1.f : 0.f, c0 + 1 == k ? 1.f : 0.f);
            }
        }
        __syncthreads();   // protect xb/bk/t2 before next tile
    }

    // ---- CTA loss contribution ----
    for (int off = 16; off; off >>= 1)
        loss_acc += __shfl_down_sync(0xffffffffu, loss_acc, off);
    if (lane == 0) red[w] = loss_acc;
    __syncthreads();
    if (tid == 0) {
        double s = 0.0;
        for (int i = 0; i < 16; ++i) s += red[i];
        atomicAdd(&g_loss, s);
    }

    // ---- Last-CTA final reduction + global state reset (replay-safe) ----
    __threadfence();
    __syncthreads();
    if (tid == 0) {
        int t = atomicAdd(&g_done, 1);
        *lastf = (t == (int)gridDim.x - 1);
    }
    __syncthreads();
    if (*lastf) {
        int c = atomicAdd(&g_counts[tid], 0);     // tid == code (512 == 512)
        double pr = (double)c * (1.0 / 262144.0);
        red[tid] = pr * log(pr + 1e-10);
        atomicExch(&g_counts[tid], 0);            // reset for next replay
        __syncthreads();
        for (int st = 256; st; st >>= 1) {
            if (tid < st) red[tid] += red[tid + st];
            __syncthreads();
        }
        if (tid == 0) {
            double L = atomicAdd(&g_loss, 0.0);
            out[O_PERP] = (float)exp(-red[0]);
            float m = (float)(L * (1.0 / 16777216.0));
            out[O_LOSS] = m + 0.25f * m;          // q_latent + 0.25 * e_latent
            atomicExch((unsigned long long*)&g_loss, 0ull);
            atomicExch(&g_done, 0);
        }
    }
}

extern "C" void kernel_launch(void* const* d_in, const int* in_sizes, int n_in,
                              void* d_out, int out_size)
{
    const float* x   = (const float*)d_in[0];   // (64, 32, 8192) fp32
    const float* emb = (const float*)d_in[1];   // (512, 64) fp32
    float* out = (float*)d_out;

    cudaFuncSetAttribute(vq_tc, cudaFuncAttributeMaxDynamicSharedMemorySize, SMEM_TOTAL);
    vq_tc<<<148, THREADS, SMEM_TOTAL>>>(x, emb, out);
}